// round 1
// baseline (speedup 1.0000x reference)
#include <cuda_runtime.h>
#include <cuda_bf16.h>
#include <math.h>

// ---------------- constants ----------------
#define BATCH 4
#define CH    128
#define HH    256
#define WW    256
#define HW    65536          // 256*256
#define WS    16
#define NWIN  256            // windows per batch (16x16)
#define CD    131            // cond channels
#define C4    32
#define C8    16

// ---------------- scratch (device globals; no allocation) ----------------
__device__ float g_cond[(size_t)BATCH * CD * HW];        // [B][131][HW]; v in ch 0..127
__device__ float g_f   [(size_t)BATCH * C4 * HW];        // [B][32][HW]
__device__ float g_fmc [(size_t)BATCH * HW];             // channel-mean of f
__device__ float g_fm  [BATCH * C4];                     // spatial mean of f
__device__ float g_ca  [BATCH * CH];                     // sigmoid channel attention
__device__ float g_off [(size_t)BATCH * 2 * HW];         // offsets
__device__ float g_sa  [(size_t)BATCH * HW];             // spatial attention
__device__ float g_mask[BATCH * NWIN];                   // hard mask per window
__device__ float g_xw  [(size_t)BATCH * CH * HW];        // warped x
__device__ float g_qw  [(size_t)BATCH * NWIN * 256 * CH];// windowed q  [win][row][c]
__device__ float g_kw  [(size_t)BATCH * NWIN * 256 * CH];// windowed k
__device__ float g_S   [(size_t)BATCH * NWIN * 256 * 256];// attention scores/probs
__device__ float g_out [(size_t)BATCH * CH * HW];        // attention merge output
__device__ float g_b1  [(size_t)BATCH * CH * HW];        // cs scratch 1
__device__ float g_b2  [(size_t)BATCH * CH * HW];        // cs scratch 2

// ---------------- generic conv1x1 GEMM ----------------
// OUT[co][p] = act( sum_ci W[co][ci] * IN[ci][p] + bias[co] )
// win_mode=1: scatter output into windowed layout [win][row][co] (for q/k proj)
__global__ __launch_bounds__(256) void gemm1x1(
    const float* __restrict__ In, int in_bstride,
    const float* __restrict__ Wt, const float* __restrict__ Bias,
    float* __restrict__ Out, int out_bstride,
    int Cin, int Cout, int act, int win_mode)
{
    __shared__ float Xs[16][68];
    __shared__ float Wsm[64][17];
    int b   = blockIdx.z;
    int p0  = blockIdx.x * 64;
    int co0 = blockIdx.y * 64;
    int tx = threadIdx.x & 15, ty = threadIdx.x >> 4;
    float acc[4][4] = {};
    const float* inb = In + (long)b * in_bstride;

    for (int k0 = 0; k0 < Cin; k0 += 16) {
#pragma unroll
        for (int l = 0; l < 4; l++) {
            int e = threadIdx.x + 256 * l;
            int k = e >> 6, px = e & 63;
            float v = 0.f;
            if (k0 + k < Cin) v = inb[(long)(k0 + k) * HW + p0 + px];
            Xs[k][px] = v;
        }
#pragma unroll
        for (int l = 0; l < 4; l++) {
            int e = threadIdx.x + 256 * l;
            int co = e >> 4, k = e & 15;
            float v = 0.f;
            if (co0 + co < Cout && k0 + k < Cin) v = Wt[(long)(co0 + co) * Cin + k0 + k];
            Wsm[co][k] = v;
        }
        __syncthreads();
#pragma unroll
        for (int k = 0; k < 16; k++) {
            float xv[4], wv[4];
#pragma unroll
            for (int j = 0; j < 4; j++) xv[j] = Xs[k][tx + 16 * j];
#pragma unroll
            for (int i = 0; i < 4; i++) wv[i] = Wsm[ty + 16 * i][k];
#pragma unroll
            for (int i = 0; i < 4; i++)
#pragma unroll
                for (int j = 0; j < 4; j++) acc[i][j] += wv[i] * xv[j];
        }
        __syncthreads();
    }
#pragma unroll
    for (int i = 0; i < 4; i++) {
        int co = co0 + ty + 16 * i;
        if (co >= Cout) continue;
        float bv = Bias[co];
#pragma unroll
        for (int j = 0; j < 4; j++) {
            int p = p0 + tx + 16 * j;
            float v = acc[i][j] + bv;
            if (act == 1) v = v > 0.f ? v : 0.2f * v;
            if (!win_mode) {
                Out[(long)b * out_bstride + (long)co * HW + p] = v;
            } else {
                int h = p >> 8, w = p & 255;
                int win = b * NWIN + (h >> 4) * 16 + (w >> 4);
                int row = (h & 15) * 16 + (w & 15);
                Out[((long)win * 256 + row) * CH + co] = v;
            }
        }
    }
}

// ---------------- condition extra channels ----------------
__global__ __launch_bounds__(256) void fill_cond(const float* __restrict__ cg)
{
    int idx = blockIdx.x * 256 + threadIdx.x;   // B*HW threads
    int b = idx >> 16, p = idx & 65535;
    int h = p >> 8, w = p & 255;
    float ly = -1.f + (2.f / 15.f) * (float)(h & 15);
    float lx = -1.f + (2.f / 15.f) * (float)(w & 15);
    long base = (long)b * CD * HW;
    g_cond[base + (long)CH * HW + p]       = cg[(long)b * HW + p];
    g_cond[base + (long)(CH + 1) * HW + p] = ly;
    g_cond[base + (long)(CH + 2) * HW + p] = lx;
}

// ---------------- offsets head (roff1 -> leaky -> roff2) ----------------
__global__ __launch_bounds__(256) void roff_kernel(
    const float* __restrict__ w1, const float* __restrict__ b1,
    const float* __restrict__ w2, const float* __restrict__ b2)
{
    __shared__ float W1[16 * 32], B1[16], W2[2 * 16], B2[2];
    int t = threadIdx.x;
    for (int i = t; i < 512; i += 256) W1[i] = w1[i];
    if (t < 16) B1[t] = b1[t];
    if (t < 32) W2[t] = w2[t];
    if (t < 2)  B2[t] = b2[t];
    __syncthreads();
    int idx = blockIdx.x * 256 + t;
    int b = idx >> 16, p = idx & 65535;
    float fv[32];
    const float* fb = g_f + (long)b * C4 * HW + p;
#pragma unroll
    for (int c = 0; c < 32; c++) fv[c] = fb[(long)c * HW];
    float o0 = B2[0], o1 = B2[1];
#pragma unroll
    for (int o = 0; o < 16; o++) {
        float h = B1[o];
#pragma unroll
        for (int c = 0; c < 32; c++) h += W1[o * 32 + c] * fv[c];
        h = h > 0.f ? h : 0.2f * h;
        o0 += W2[o] * h;
        o1 += W2[16 + o] * h;
    }
    g_off[(long)b * 2 * HW + p]      = o0;
    g_off[(long)b * 2 * HW + HW + p] = o1;
}

// ---------------- channel-mean of f (per pixel) ----------------
__global__ __launch_bounds__(256) void fmc_kernel()
{
    int idx = blockIdx.x * 256 + threadIdx.x;
    int b = idx >> 16, p = idx & 65535;
    const float* fb = g_f + (long)b * C4 * HW + p;
    float s = 0.f;
#pragma unroll
    for (int c = 0; c < 32; c++) s += fb[(long)c * HW];
    g_fmc[idx] = s * (1.f / 32.f);
}

// ---------------- spatial mean of f ----------------
__global__ __launch_bounds__(256) void fm_kernel()
{
    int bc = blockIdx.x;                       // b*32 + c
    const float* src = g_f + (long)bc * HW;
    float s = 0.f;
    for (int i = threadIdx.x; i < HW; i += 256) s += src[i];
    __shared__ float red[256];
    red[threadIdx.x] = s; __syncthreads();
    for (int st = 128; st > 0; st >>= 1) {
        if (threadIdx.x < st) red[threadIdx.x] += red[threadIdx.x + st];
        __syncthreads();
    }
    if (threadIdx.x == 0) g_fm[bc] = red[0] * (1.f / 65536.f);
}

__global__ void ca_kernel(const float* __restrict__ w, const float* __restrict__ bias)
{
    int t = threadIdx.x;                       // 512 threads
    int b = t >> 7, co = t & 127;
    float a = bias[co];
#pragma unroll
    for (int k = 0; k < 32; k++) a += w[co * 32 + k] * g_fm[b * 32 + k];
    g_ca[t] = 1.f / (1.f + expf(-a));
}

// ---------------- spatial attention (3x3 conv, 32->1, sigmoid) ----------------
__global__ __launch_bounds__(256) void sa_kernel(const float* __restrict__ w, const float* __restrict__ bias)
{
    __shared__ float Wsm[32 * 9];
    for (int i = threadIdx.x; i < 288; i += 256) Wsm[i] = w[i];
    __syncthreads();
    int idx = blockIdx.x * 256 + threadIdx.x;
    int b = idx >> 16, p = idx & 65535;
    int h = p >> 8, wc = p & 255;
    float acc = bias[0];
    const float* fb = g_f + (long)b * C4 * HW;
    for (int c = 0; c < 32; c++) {
        const float* fc = fb + (long)c * HW;
#pragma unroll
        for (int kh = 0; kh < 3; kh++) {
            int hh = h + kh - 1;
            if ((unsigned)hh >= 256u) continue;
#pragma unroll
            for (int kw = 0; kw < 3; kw++) {
                int ww = wc + kw - 1;
                if ((unsigned)ww >= 256u) continue;
                acc += fc[hh * 256 + ww] * Wsm[c * 9 + kh * 3 + kw];
            }
        }
    }
    g_sa[idx] = 1.f / (1.f + expf(-acc));
}

// ---------------- window mask (predictor MLP + gumbel argmax) ----------------
__global__ __launch_bounds__(256) void mask_kernel(
    const float* __restrict__ rm1w, const float* __restrict__ rm1b,
    const float* __restrict__ rm2w, const float* __restrict__ rm2b,
    const float* __restrict__ gu)
{
    __shared__ float mw[256];
    __shared__ float hs[16];
    int win = blockIdx.x;
    int b = win >> 8, n = win & 255;
    int wy = n >> 4, wx = n & 15;
    int e = threadIdx.x;
    int dh = e >> 4, dw = e & 15;
    int p = (wy * 16 + dh) * 256 + wx * 16 + dw;
    mw[e] = g_fmc[(long)b * HW + p];
    __syncthreads();
    if (e < 16) {
        float h = rm1b[e];
        for (int k = 0; k < 256; k++) h += rm1w[e * 256 + k] * mw[k];
        hs[e] = h > 0.f ? h : 0.2f * h;
    }
    __syncthreads();
    if (e == 0) {
        float l0 = rm2b[0], l1 = rm2b[1];
#pragma unroll
        for (int k = 0; k < 16; k++) { l0 += rm2w[k] * hs[k]; l1 += rm2w[16 + k] * hs[k]; }
        float m = fmaxf(l0, l1);
        float p0 = expf(l0 - m), p1 = expf(l1 - m);
        float s = p0 + p1; p0 /= s; p1 /= s;
        float u0 = gu[(long)win * 2 + 0], u1 = gu[(long)win * 2 + 1];
        float q0 = -logf(-logf(u0 + 1e-10f) + 1e-10f);
        float q1 = -logf(-logf(u1 + 1e-10f) + 1e-10f);
        // argmax over softmax(pred+g) == argmax(pred+g); index 0 wins ties
        g_mask[win] = (p0 + q0 >= p1 + q1) ? 1.f : 0.f;
    }
}

// ---------------- bilinear flow warp ----------------
__global__ __launch_bounds__(256) void warp_kernel(const float* __restrict__ x)
{
    int idx = blockIdx.x * 256 + threadIdx.x;
    int b = idx >> 16, p = idx & 65535;
    int h = p >> 8, w = p & 255;
    float fx = g_off[(long)b * 2 * HW + p];
    float fy = g_off[(long)b * 2 * HW + HW + p];
    float sx = fminf(fmaxf((float)w + fx, 0.f), 255.f);
    float sy = fminf(fmaxf((float)h + fy, 0.f), 255.f);
    float x0f = floorf(sx), y0f = floorf(sy);
    float x1f = fminf(x0f + 1.f, 255.f), y1f = fminf(y0f + 1.f, 255.f);
    float wx = sx - x0f, wy = sy - y0f;
    int x0 = (int)x0f, x1 = (int)x1f, y0 = (int)y0f, y1 = (int)y1f;
    float w00 = (1.f - wx) * (1.f - wy), w01 = wx * (1.f - wy);
    float w10 = (1.f - wx) * wy,        w11 = wx * wy;
    int i00 = y0 * 256 + x0, i01 = y0 * 256 + x1;
    int i10 = y1 * 256 + x0, i11 = y1 * 256 + x1;
    const float* xb = x + (long)b * CH * HW;
    float* ob = g_xw + (long)b * CH * HW;
    for (int c = 0; c < CH; c++) {
        const float* xc = xb + (long)c * HW;
        ob[(long)c * HW + p] = w00 * xc[i00] + w01 * xc[i01] + w10 * xc[i10] + w11 * xc[i11];
    }
}

// ---------------- S = Q K^T per masked window ----------------
__global__ __launch_bounds__(256) void sgemm_kernel()
{
    int win = blockIdx.y;
    if (g_mask[win] == 0.f) return;
    __shared__ float As[64][17];
    __shared__ float Bs[64][17];
    int tile = blockIdx.x;                      // 16 tiles: 4x4 of 64x64
    int i0 = (tile >> 2) * 64, j0 = (tile & 3) * 64;
    int tx = threadIdx.x & 15, ty = threadIdx.x >> 4;
    const float* A  = g_qw + (long)win * 256 * CH;
    const float* Bm = g_kw + (long)win * 256 * CH;
    float acc[4][4] = {};
    for (int k0 = 0; k0 < CH; k0 += 16) {
#pragma unroll
        for (int l = 0; l < 4; l++) {
            int e = threadIdx.x + 256 * l;
            int r = e >> 4, k = e & 15;
            As[r][k] = A [(long)(i0 + r) * CH + k0 + k];
            Bs[r][k] = Bm[(long)(j0 + r) * CH + k0 + k];
        }
        __syncthreads();
#pragma unroll
        for (int k = 0; k < 16; k++) {
            float av[4], bv[4];
#pragma unroll
            for (int i = 0; i < 4; i++) av[i] = As[ty + 16 * i][k];
#pragma unroll
            for (int j = 0; j < 4; j++) bv[j] = Bs[tx + 16 * j][k];
#pragma unroll
            for (int i = 0; i < 4; i++)
#pragma unroll
                for (int j = 0; j < 4; j++) acc[i][j] += av[i] * bv[j];
        }
        __syncthreads();
    }
    float* Sw = g_S + (long)win * 65536;
#pragma unroll
    for (int i = 0; i < 4; i++)
#pragma unroll
        for (int j = 0; j < 4; j++)
            Sw[(long)(i0 + ty + 16 * i) * 256 + j0 + tx + 16 * j] = acc[i][j];
}

// ---------------- row softmax on S ----------------
__global__ __launch_bounds__(256) void softmax_kernel()
{
    int win = blockIdx.x;
    if (g_mask[win] == 0.f) return;
    int warp = threadIdx.x >> 5, lane = threadIdx.x & 31;
    float* Sw = g_S + (long)win * 65536;
    for (int row = warp; row < 256; row += 8) {
        float* r = Sw + row * 256;
        float v[8];
        float mx = -1e30f;
#pragma unroll
        for (int k = 0; k < 8; k++) { v[k] = r[lane + 32 * k]; mx = fmaxf(mx, v[k]); }
#pragma unroll
        for (int o = 16; o > 0; o >>= 1) mx = fmaxf(mx, __shfl_xor_sync(0xffffffffu, mx, o));
        float s = 0.f;
#pragma unroll
        for (int k = 0; k < 8; k++) { v[k] = expf(v[k] - mx); s += v[k]; }
#pragma unroll
        for (int o = 16; o > 0; o >>= 1) s += __shfl_xor_sync(0xffffffffu, s, o);
        float inv = 1.f / s;
#pragma unroll
        for (int k = 0; k < 8; k++) r[lane + 32 * k] = v[k] * inv;
    }
}

// ---------------- out = P @ V (masked) or v*sa (unmasked), scattered to NCHW ----------------
__global__ __launch_bounds__(256) void pv_kernel()
{
    int win = blockIdx.y;
    int b = win >> 8, n = win & 255;
    int wy = n >> 4, wx = n & 15;
    int tile = blockIdx.x;                      // 8 tiles: (i-tile 0..3, c-tile 0..1)
    int i0 = (tile >> 1) * 64, c0 = (tile & 1) * 64;
    int tx = threadIdx.x & 15, ty = threadIdx.x >> 4;
    const float* vbase = g_cond + (long)b * CD * HW;   // v = first 128 channels of cond

    if (g_mask[win] == 0.f) {
#pragma unroll
        for (int ii = 0; ii < 4; ii++)
#pragma unroll
            for (int jj = 0; jj < 4; jj++) {
                int c = c0 + ty + 16 * ii;
                int i = i0 + tx + 16 * jj;
                int p = (wy * 16 + (i >> 4)) * 256 + wx * 16 + (i & 15);
                g_out[(long)b * CH * HW + (long)c * HW + p] =
                    vbase[(long)c * HW + p] * g_sa[(long)b * HW + p];
            }
        return;
    }

    __shared__ float Ps[64][17];
    __shared__ float Vs[16][65];
    const float* Pm = g_S + (long)win * 65536;
    float acc[4][4] = {};
    for (int k0 = 0; k0 < 256; k0 += 16) {
#pragma unroll
        for (int l = 0; l < 4; l++) {
            int e = threadIdx.x + 256 * l;
            int r = e >> 4, k = e & 15;
            Ps[r][k] = Pm[(long)(i0 + r) * 256 + k0 + k];
        }
#pragma unroll
        for (int l = 0; l < 4; l++) {
            int ee = threadIdx.x + 256 * l;
            int cl = ee >> 4, jl = ee & 15;
            int j = k0 + jl;
            int p = (wy * 16 + (j >> 4)) * 256 + wx * 16 + (j & 15);
            Vs[jl][cl] = vbase[(long)(c0 + cl) * HW + p];
        }
        __syncthreads();
#pragma unroll
        for (int k = 0; k < 16; k++) {
            float pv[4], vv[4];
#pragma unroll
            for (int jj = 0; jj < 4; jj++) pv[jj] = Ps[tx + 16 * jj][k];
#pragma unroll
            for (int ii = 0; ii < 4; ii++) vv[ii] = Vs[k][ty + 16 * ii];
#pragma unroll
            for (int ii = 0; ii < 4; ii++)
#pragma unroll
                for (int jj = 0; jj < 4; jj++) acc[ii][jj] += pv[jj] * vv[ii];
        }
        __syncthreads();
    }
#pragma unroll
    for (int ii = 0; ii < 4; ii++)
#pragma unroll
        for (int jj = 0; jj < 4; jj++) {
            int c = c0 + ty + 16 * ii;
            int i = i0 + tx + 16 * jj;
            int p = (wy * 16 + (i >> 4)) * 256 + wx * 16 + (i & 15);
            g_out[(long)b * CH * HW + (long)c * HW + p] = acc[ii][jj];
        }
}

// ---------------- depthwise 5x5 ----------------
__global__ __launch_bounds__(256) void dw5_kernel(
    const float* __restrict__ In, const float* __restrict__ Wt,
    const float* __restrict__ Bias, float* __restrict__ Out, int dil)
{
    long idx = (long)blockIdx.x * 256 + threadIdx.x;    // B*C*HW
    int p = (int)(idx & 65535);
    int bc = (int)(idx >> 16);
    int c = bc & 127;
    int h = p >> 8, w = p & 255;
    const float* ib = In + (long)bc * HW;
    float acc = Bias[c];
#pragma unroll
    for (int kh = 0; kh < 5; kh++) {
        int hh = h + (kh - 2) * dil;
        if ((unsigned)hh >= 256u) continue;
#pragma unroll
        for (int kw = 0; kw < 5; kw++) {
            int ww = w + (kw - 2) * dil;
            if ((unsigned)ww >= 256u) continue;
            acc += ib[hh * 256 + ww] * Wt[c * 25 + kh * 5 + kw];
        }
    }
    Out[idx] = acc;
}

// ---------------- depthwise 5x5 dil3 + gelu*ca + residual ----------------
__global__ __launch_bounds__(256) void dw5_gelu_kernel(
    const float* __restrict__ In, const float* __restrict__ Wt,
    const float* __restrict__ Bias, float* __restrict__ Out)
{
    long idx = (long)blockIdx.x * 256 + threadIdx.x;
    int p = (int)(idx & 65535);
    int bc = (int)(idx >> 16);
    int c = bc & 127;
    int h = p >> 8, w = p & 255;
    const float* ib = In + (long)bc * HW;
    float acc = Bias[c];
#pragma unroll
    for (int kh = 0; kh < 5; kh++) {
        int hh = h + (kh - 2) * 3;
        if ((unsigned)hh >= 256u) continue;
#pragma unroll
        for (int kw = 0; kw < 5; kw++) {
            int ww = w + (kw - 2) * 3;
            if ((unsigned)ww >= 256u) continue;
            acc += ib[hh * 256 + ww] * Wt[c * 25 + kh * 5 + kw];
        }
    }
    float ge = 0.5f * acc * (1.f + erff(acc * 0.70710678118654752f));
    Out[idx] = ge * g_ca[bc] + g_out[idx];
}

// ---------------- launcher ----------------
extern "C" void kernel_launch(void* const* d_in, const int* in_sizes, int n_in,
                              void* d_out, int out_size)
{
    const float* x    = (const float*)d_in[0];
    const float* cg   = (const float*)d_in[1];
    const float* gu   = (const float*)d_in[2];
    const float* pv_w = (const float*)d_in[3];
    const float* pv_b = (const float*)d_in[4];
    const float* pq_w = (const float*)d_in[5];
    const float* pq_b = (const float*)d_in[6];
    const float* pk_w = (const float*)d_in[7];
    const float* pk_b = (const float*)d_in[8];
    const float* cs1_w = (const float*)d_in[9];
    const float* cs1_b = (const float*)d_in[10];
    const float* cs2_w = (const float*)d_in[11];
    const float* cs2_b = (const float*)d_in[12];
    const float* cs3_w = (const float*)d_in[13];
    const float* cs3_b = (const float*)d_in[14];
    const float* po_w  = (const float*)d_in[15];
    const float* po_b  = (const float*)d_in[16];
    const float* rin_w = (const float*)d_in[17];
    const float* rin_b = (const float*)d_in[18];
    const float* roff1_w = (const float*)d_in[19];
    const float* roff1_b = (const float*)d_in[20];
    const float* roff2_w = (const float*)d_in[21];
    const float* roff2_b = (const float*)d_in[22];
    const float* rm1_w = (const float*)d_in[23];
    const float* rm1_b = (const float*)d_in[24];
    const float* rm2_w = (const float*)d_in[25];
    const float* rm2_b = (const float*)d_in[26];
    const float* rca_w = (const float*)d_in[27];
    const float* rca_b = (const float*)d_in[28];
    const float* rsa_w = (const float*)d_in[29];
    const float* rsa_b = (const float*)d_in[30];
    float* out = (float*)d_out;

    float *p_cond, *p_f, *p_xw, *p_qw, *p_kw, *p_out, *p_b1, *p_b2;
    cudaGetSymbolAddress((void**)&p_cond, g_cond);
    cudaGetSymbolAddress((void**)&p_f,    g_f);
    cudaGetSymbolAddress((void**)&p_xw,   g_xw);
    cudaGetSymbolAddress((void**)&p_qw,   g_qw);
    cudaGetSymbolAddress((void**)&p_kw,   g_kw);
    cudaGetSymbolAddress((void**)&p_out,  g_out);
    cudaGetSymbolAddress((void**)&p_b1,   g_b1);
    cudaGetSymbolAddress((void**)&p_b2,   g_b2);

    dim3 blk(256);

    // 1. v = pv conv  -> cond channels 0..127
    gemm1x1<<<dim3(HW / 64, 2, BATCH), blk>>>(x, CH * HW, pv_w, pv_b,
                                              p_cond, CD * HW, CH, CH, 0, 0);
    // 2. cond extra channels
    fill_cond<<<BATCH * HW / 256, blk>>>(cg);
    // 3. f = leaky(rin conv)
    gemm1x1<<<dim3(HW / 64, 1, BATCH), blk>>>(p_cond, CD * HW, rin_w, rin_b,
                                              p_f, C4 * HW, CD, C4, 1, 0);
    // 4. offsets
    roff_kernel<<<BATCH * HW / 256, blk>>>(roff1_w, roff1_b, roff2_w, roff2_b);
    // 5. predictor stats
    fmc_kernel<<<BATCH * HW / 256, blk>>>();
    fm_kernel<<<BATCH * C4, blk>>>();
    ca_kernel<<<1, BATCH * CH>>>(rca_w, rca_b);
    sa_kernel<<<BATCH * HW / 256, blk>>>(rsa_w, rsa_b);
    // 6. hard mask
    mask_kernel<<<BATCH * NWIN, blk>>>(rm1_w, rm1_b, rm2_w, rm2_b, gu);
    // 7. flow warp
    warp_kernel<<<BATCH * HW / 256, blk>>>(x);
    // 8. q/k projections into windowed layout
    gemm1x1<<<dim3(HW / 64, 2, BATCH), blk>>>(p_xw, CH * HW, pq_w, pq_b,
                                              p_qw, 0, CH, CH, 0, 1);
    gemm1x1<<<dim3(HW / 64, 2, BATCH), blk>>>(p_xw, CH * HW, pk_w, pk_b,
                                              p_kw, 0, CH, CH, 0, 1);
    // 9. attention
    sgemm_kernel<<<dim3(16, BATCH * NWIN), blk>>>();
    softmax_kernel<<<BATCH * NWIN, blk>>>();
    pv_kernel<<<dim3(8, BATCH * NWIN), blk>>>();
    // 10. cs chain
    gemm1x1<<<dim3(HW / 64, 2, BATCH), blk>>>(p_out, CH * HW, cs1_w, cs1_b,
                                              p_b1, CH * HW, CH, CH, 0, 0);
    dw5_kernel<<<(BATCH * CH * HW) / 256, blk>>>(p_b1, cs2_w, cs2_b, p_b2, 1);
    dw5_gelu_kernel<<<(BATCH * CH * HW) / 256, blk>>>(p_b2, cs3_w, cs3_b, p_b1);
    // 11. final projection
    gemm1x1<<<dim3(HW / 64, 2, BATCH), blk>>>(p_b1, CH * HW, po_w, po_b,
                                              out, CH * HW, CH, CH, 0, 0);
    (void)in_sizes; (void)n_in; (void)out_size;
}

// round 4
// speedup vs baseline: 1.1991x; 1.1991x over previous
#include <cuda_runtime.h>
#include <cuda_bf16.h>
#include <math.h>
#include <stdint.h>

// ---------------- constants ----------------
#define BATCH 4
#define CH    128
#define HW    65536          // 256*256
#define WS    16
#define NWIN  256            // windows per batch (16x16)
#define CD    131            // cond channels
#define C4    32
#define C8    16

// ---------------- scratch (device globals; no allocation) ----------------
__device__ float g_cond[(size_t)BATCH * CD * HW];
__device__ float g_f   [(size_t)BATCH * C4 * HW];
__device__ float g_fmc [(size_t)BATCH * HW];
__device__ float g_fm  [BATCH * C4];
__device__ float g_ca  [BATCH * CH];
__device__ float g_off [(size_t)BATCH * 2 * HW];
__device__ float g_sa  [(size_t)BATCH * HW];
__device__ float g_mask[BATCH * NWIN];
__device__ float g_xw  [(size_t)BATCH * CH * HW];
__device__ float g_qw  [(size_t)BATCH * NWIN * 256 * CH];
__device__ float g_kw  [(size_t)BATCH * NWIN * 256 * CH];
__device__ float g_S   [(size_t)BATCH * NWIN * 256 * 256];
__device__ float g_out [(size_t)BATCH * CH * HW];
__device__ float g_b1  [(size_t)BATCH * CH * HW];
__device__ float g_b2  [(size_t)BATCH * CH * HW];
__device__ __nv_bfloat16 g_whi[CH * CH];
__device__ __nv_bfloat16 g_wlo[CH * CH];

// =====================================================================
// mma.sync helpers (baseline PTX ISA — valid on sm_103 target)
// =====================================================================
__device__ __forceinline__ uint32_t smem_u32(const void* p) {
    uint32_t a;
    asm("{ .reg .u64 t; cvta.to.shared.u64 t, %1; cvt.u32.u64 %0, t; }"
        : "=r"(a) : "l"(p));
    return a;
}

__device__ __forceinline__ void ldsm4(uint32_t& r0, uint32_t& r1, uint32_t& r2, uint32_t& r3,
                                      uint32_t addr) {
    asm volatile("ldmatrix.sync.aligned.m8n8.x4.shared.b16 {%0,%1,%2,%3}, [%4];"
                 : "=r"(r0), "=r"(r1), "=r"(r2), "=r"(r3) : "r"(addr));
}

__device__ __forceinline__ void mma_bf16(float* d, const uint32_t* a, uint32_t b0, uint32_t b1) {
    asm volatile("mma.sync.aligned.m16n8k16.row.col.f32.bf16.bf16.f32 "
                 "{%0,%1,%2,%3},{%4,%5,%6,%7},{%8,%9},{%0,%1,%2,%3};"
                 : "+f"(d[0]), "+f"(d[1]), "+f"(d[2]), "+f"(d[3])
                 : "r"(a[0]), "r"(a[1]), "r"(a[2]), "r"(a[3]), "r"(b0), "r"(b1));
}

// swizzled smem offset for [row][k] bf16, 128 k per row (256B rows)
__device__ __forceinline__ uint32_t swz(int row, int k) {
    return (uint32_t)(row * 256 + ((((k >> 3) ^ (row & 7))) << 4) + ((k & 7) << 1));
}

// ---------------- W pre-split: fp32 [128][128] -> bf16 hi/lo ----------------
__global__ __launch_bounds__(256) void w_prep(const float* __restrict__ W,
                                              __nv_bfloat16* __restrict__ Whi,
                                              __nv_bfloat16* __restrict__ Wlo)
{
    int i = blockIdx.x * 256 + threadIdx.x;
    float x = W[i];
    __nv_bfloat16 h = __float2bfloat16(x);
    Whi[i] = h;
    Wlo[i] = __float2bfloat16(x - __bfloat162float(h));
}

// =====================================================================
// Tensor-core (HMMA) 1x1 conv: Out[co][px] = sum_ci W[co][ci] In[ci][px] + b
// bf16 hi/lo split (3 terms). win_mode=1 -> scatter to [win][row][co].
// Block: 256 thr (8 warps: 4 m x 2 n), tile M=128 co, N=128 px, K=128.
// =====================================================================
#define WHI_OFF 0
#define WLO_OFF 32768
#define XHI_OFF 65536
#define XLO_OFF 98304
#define CONV_SMEM 131072
#define TPB_CONV 2

__global__ __launch_bounds__(256) void conv_mma(
    const float* __restrict__ In, long in_bstride,
    const __nv_bfloat16* __restrict__ Whi, const __nv_bfloat16* __restrict__ Wlo,
    const float* __restrict__ Bias,
    float* __restrict__ Out, long out_bstride, int win_mode)
{
    extern __shared__ char smc[];
    uint32_t sbase = smem_u32(smc);
    int tid = threadIdx.x, lane = tid & 31, wid = tid >> 5;
    int wm = wid & 3, wn = wid >> 2;          // warp tile: 32 m x 64 n
    int g = lane >> 2, q = lane & 3;

    // ---- load W hi/lo into swizzled smem (uint4 = one 16B chunk) ----
    for (int idx = tid; idx < 2048; idx += 256) {
        int co = idx >> 4, ch = idx & 15;
        uint32_t off = (uint32_t)co * 256u + (uint32_t)((ch ^ (co & 7)) << 4);
        *(uint4*)(smc + WHI_OFF + off) = ((const uint4*)Whi)[idx];
        *(uint4*)(smc + WLO_OFF + off) = ((const uint4*)Wlo)[idx];
    }

    for (int t = 0; t < TPB_CONV; t++) {
        int tile = blockIdx.x * TPB_CONV + t;
        int b = tile >> 9;
        int p0 = (tile & 511) << 7;
        const float* inb = In + (long)b * in_bstride + p0;

        __syncthreads();   // protect X smem from previous-tile readers (also orders W load)

        // ---- convert X tile: In[k][p0+px] -> Xsm[px][k] hi/lo ----
#pragma unroll 4
        for (int it = 0; it < 16; it++) {
            int k = wid * 16 + it;
            float4 v = *(const float4*)(inb + (long)k * HW + lane * 4);
            float xs[4] = {v.x, v.y, v.z, v.w};
#pragma unroll
            for (int e = 0; e < 4; e++) {
                int px = lane * 4 + e;
                float x = xs[e];
                __nv_bfloat16 h = __float2bfloat16(x);
                __nv_bfloat16 l = __float2bfloat16(x - __bfloat162float(h));
                uint32_t off = swz(px, k);
                *(__nv_bfloat16*)(smc + XHI_OFF + off) = h;
                *(__nv_bfloat16*)(smc + XLO_OFF + off) = l;
            }
        }
        __syncthreads();

        // ---- compute: 3 terms x 8 k-steps ----
        float acc[2][8][4] = {};
#pragma unroll
        for (int term = 0; term < 3; term++) {
            uint32_t a_base = sbase + (term == 2 ? WLO_OFF : WHI_OFF);
            uint32_t b_base = sbase + (term == 1 ? XLO_OFF : XHI_OFF);
#pragma unroll
            for (int k0 = 0; k0 < 128; k0 += 16) {
                int kk = k0 + ((lane >> 4) << 3);
                uint32_t a[2][4];
#pragma unroll
                for (int mf = 0; mf < 2; mf++)
                    ldsm4(a[mf][0], a[mf][1], a[mf][2], a[mf][3],
                          a_base + swz(wm * 32 + mf * 16 + (lane & 15), kk));
                uint32_t bf[4][4];
#pragma unroll
                for (int nb = 0; nb < 4; nb++)
                    ldsm4(bf[nb][0], bf[nb][1], bf[nb][2], bf[nb][3],
                          b_base + swz(wn * 64 + nb * 16 + (lane & 15), kk));
#pragma unroll
                for (int mf = 0; mf < 2; mf++)
#pragma unroll
                    for (int nb = 0; nb < 4; nb++) {
                        mma_bf16(acc[mf][nb * 2 + 0], a[mf], bf[nb][0], bf[nb][2]);
                        mma_bf16(acc[mf][nb * 2 + 1], a[mf], bf[nb][1], bf[nb][3]);
                    }
            }
        }

        // ---- epilogue ----
        if (!win_mode) {
            float* ob = Out + (long)b * out_bstride;
#pragma unroll
            for (int mf = 0; mf < 2; mf++) {
                int co0 = wm * 32 + mf * 16 + g;
                float bv0 = Bias[co0], bv1 = Bias[co0 + 8];
                float* r0 = ob + (long)co0 * HW + p0;
                float* r1 = ob + (long)(co0 + 8) * HW + p0;
#pragma unroll
                for (int nf = 0; nf < 8; nf++) {
                    int col = wn * 64 + nf * 8 + q * 2;
                    float2 v0 = {acc[mf][nf][0] + bv0, acc[mf][nf][1] + bv0};
                    float2 v1 = {acc[mf][nf][2] + bv1, acc[mf][nf][3] + bv1};
                    *(float2*)(r0 + col) = v0;
                    *(float2*)(r1 + col) = v1;
                }
            }
        } else {
#pragma unroll
            for (int mf = 0; mf < 2; mf++) {
                int co0 = wm * 32 + mf * 16 + g;
                float bv0 = Bias[co0], bv1 = Bias[co0 + 8];
#pragma unroll
                for (int nf = 0; nf < 8; nf++) {
#pragma unroll
                    for (int e = 0; e < 2; e++) {
                        int p = p0 + wn * 64 + nf * 8 + q * 2 + e;
                        int h = p >> 8, w = p & 255;
                        long a0 = ((long)(b * NWIN + (h >> 4) * 16 + (w >> 4)) * 256
                                   + (h & 15) * 16 + (w & 15)) * CH;
                        Out[a0 + co0]     = acc[mf][nf][e]     + bv0;
                        Out[a0 + co0 + 8] = acc[mf][nf][e + 2] + bv1;
                    }
                }
            }
        }
    }
}

// =====================================================================
// fp32 generic conv1x1 GEMM (kept for rin: 131 -> 32)
// =====================================================================
__global__ __launch_bounds__(256) void gemm1x1(
    const float* __restrict__ In, int in_bstride,
    const float* __restrict__ Wt, const float* __restrict__ Bias,
    float* __restrict__ Out, int out_bstride,
    int Cin, int Cout, int act)
{
    __shared__ float Xs[16][68];
    __shared__ float Wsm[64][17];
    int b   = blockIdx.z;
    int p0  = blockIdx.x * 64;
    int co0 = blockIdx.y * 64;
    int tx = threadIdx.x & 15, ty = threadIdx.x >> 4;
    float acc[4][4] = {};
    const float* inb = In + (long)b * in_bstride;

    for (int k0 = 0; k0 < Cin; k0 += 16) {
#pragma unroll
        for (int l = 0; l < 4; l++) {
            int e = threadIdx.x + 256 * l;
            int k = e >> 6, px = e & 63;
            float v = 0.f;
            if (k0 + k < Cin) v = inb[(long)(k0 + k) * HW + p0 + px];
            Xs[k][px] = v;
        }
#pragma unroll
        for (int l = 0; l < 4; l++) {
            int e = threadIdx.x + 256 * l;
            int co = e >> 4, k = e & 15;
            float v = 0.f;
            if (co0 + co < Cout && k0 + k < Cin) v = Wt[(long)(co0 + co) * Cin + k0 + k];
            Wsm[co][k] = v;
        }
        __syncthreads();
#pragma unroll
        for (int k = 0; k < 16; k++) {
            float xv[4], wv[4];
#pragma unroll
            for (int j = 0; j < 4; j++) xv[j] = Xs[k][tx + 16 * j];
#pragma unroll
            for (int i = 0; i < 4; i++) wv[i] = Wsm[ty + 16 * i][k];
#pragma unroll
            for (int i = 0; i < 4; i++)
#pragma unroll
                for (int j = 0; j < 4; j++) acc[i][j] += wv[i] * xv[j];
        }
        __syncthreads();
    }
#pragma unroll
    for (int i = 0; i < 4; i++) {
        int co = co0 + ty + 16 * i;
        if (co >= Cout) continue;
        float bv = Bias[co];
#pragma unroll
        for (int j = 0; j < 4; j++) {
            int p = p0 + tx + 16 * j;
            float v = acc[i][j] + bv;
            if (act == 1) v = v > 0.f ? v : 0.2f * v;
            Out[(long)b * out_bstride + (long)co * HW + p] = v;
        }
    }
}

// ---------------- condition extra channels ----------------
__global__ __launch_bounds__(256) void fill_cond(const float* __restrict__ cg)
{
    int idx = blockIdx.x * 256 + threadIdx.x;
    int b = idx >> 16, p = idx & 65535;
    int h = p >> 8, w = p & 255;
    float ly = -1.f + (2.f / 15.f) * (float)(h & 15);
    float lx = -1.f + (2.f / 15.f) * (float)(w & 15);
    long base = (long)b * CD * HW;
    g_cond[base + (long)CH * HW + p]       = cg[(long)b * HW + p];
    g_cond[base + (long)(CH + 1) * HW + p] = ly;
    g_cond[base + (long)(CH + 2) * HW + p] = lx;
}

// ---------------- offsets head ----------------
__global__ __launch_bounds__(256) void roff_kernel(
    const float* __restrict__ w1, const float* __restrict__ b1,
    const float* __restrict__ w2, const float* __restrict__ b2)
{
    __shared__ float W1[16 * 32], B1[16], W2[2 * 16], B2[2];
    int t = threadIdx.x;
    for (int i = t; i < 512; i += 256) W1[i] = w1[i];
    if (t < 16) B1[t] = b1[t];
    if (t < 32) W2[t] = w2[t];
    if (t < 2)  B2[t] = b2[t];
    __syncthreads();
    int idx = blockIdx.x * 256 + t;
    int b = idx >> 16, p = idx & 65535;
    float fv[32];
    const float* fb = g_f + (long)b * C4 * HW + p;
#pragma unroll
    for (int c = 0; c < 32; c++) fv[c] = fb[(long)c * HW];
    float o0 = B2[0], o1 = B2[1];
#pragma unroll
    for (int o = 0; o < 16; o++) {
        float h = B1[o];
#pragma unroll
        for (int c = 0; c < 32; c++) h += W1[o * 32 + c] * fv[c];
        h = h > 0.f ? h : 0.2f * h;
        o0 += W2[o] * h;
        o1 += W2[16 + o] * h;
    }
    g_off[(long)b * 2 * HW + p]      = o0;
    g_off[(long)b * 2 * HW + HW + p] = o1;
}

// ---------------- channel-mean of f ----------------
__global__ __launch_bounds__(256) void fmc_kernel()
{
    int idx = blockIdx.x * 256 + threadIdx.x;
    int b = idx >> 16, p = idx & 65535;
    const float* fb = g_f + (long)b * C4 * HW + p;
    float s = 0.f;
#pragma unroll
    for (int c = 0; c < 32; c++) s += fb[(long)c * HW];
    g_fmc[idx] = s * (1.f / 32.f);
}

// ---------------- spatial mean of f ----------------
__global__ __launch_bounds__(256) void fm_kernel()
{
    int bc = blockIdx.x;
    const float* src = g_f + (long)bc * HW;
    float s = 0.f;
    for (int i = threadIdx.x; i < HW; i += 256) s += src[i];
    __shared__ float red[256];
    red[threadIdx.x] = s; __syncthreads();
    for (int st = 128; st > 0; st >>= 1) {
        if (threadIdx.x < st) red[threadIdx.x] += red[threadIdx.x + st];
        __syncthreads();
    }
    if (threadIdx.x == 0) g_fm[bc] = red[0] * (1.f / 65536.f);
}

__global__ void ca_kernel(const float* __restrict__ w, const float* __restrict__ bias)
{
    int t = threadIdx.x;
    int b = t >> 7, co = t & 127;
    float a = bias[co];
#pragma unroll
    for (int k = 0; k < 32; k++) a += w[co * 32 + k] * g_fm[b * 32 + k];
    g_ca[t] = 1.f / (1.f + expf(-a));
}

// ---------------- spatial attention ----------------
__global__ __launch_bounds__(256) void sa_kernel(const float* __restrict__ w, const float* __restrict__ bias)
{
    __shared__ float Wsm[32 * 9];
    for (int i = threadIdx.x; i < 288; i += 256) Wsm[i] = w[i];
    __syncthreads();
    int idx = blockIdx.x * 256 + threadIdx.x;
    int b = idx >> 16, p = idx & 65535;
    int h = p >> 8, wc = p & 255;
    float acc = bias[0];
    const float* fb = g_f + (long)b * C4 * HW;
    for (int c = 0; c < 32; c++) {
        const float* fc = fb + (long)c * HW;
#pragma unroll
        for (int kh = 0; kh < 3; kh++) {
            int hh = h + kh - 1;
            if ((unsigned)hh >= 256u) continue;
#pragma unroll
            for (int kw = 0; kw < 3; kw++) {
                int ww = wc + kw - 1;
                if ((unsigned)ww >= 256u) continue;
                acc += fc[hh * 256 + ww] * Wsm[c * 9 + kh * 3 + kw];
            }
        }
    }
    g_sa[idx] = 1.f / (1.f + expf(-acc));
}

// ---------------- window mask ----------------
__global__ __launch_bounds__(256) void mask_kernel(
    const float* __restrict__ rm1w, const float* __restrict__ rm1b,
    const float* __restrict__ rm2w, const float* __restrict__ rm2b,
    const float* __restrict__ gu)
{
    __shared__ float mw[256];
    __shared__ float hs[16];
    int win = blockIdx.x;
    int b = win >> 8, n = win & 255;
    int wy = n >> 4, wx = n & 15;
    int e = threadIdx.x;
    int dh = e >> 4, dw = e & 15;
    int p = (wy * 16 + dh) * 256 + wx * 16 + dw;
    mw[e] = g_fmc[(long)b * HW + p];
    __syncthreads();
    if (e < 16) {
        float h = rm1b[e];
        for (int k = 0; k < 256; k++) h += rm1w[e * 256 + k] * mw[k];
        hs[e] = h > 0.f ? h : 0.2f * h;
    }
    __syncthreads();
    if (e == 0) {
        float l0 = rm2b[0], l1 = rm2b[1];
#pragma unroll
        for (int k = 0; k < 16; k++) { l0 += rm2w[k] * hs[k]; l1 += rm2w[16 + k] * hs[k]; }
        float m = fmaxf(l0, l1);
        float p0 = expf(l0 - m), p1 = expf(l1 - m);
        float s = p0 + p1; p0 /= s; p1 /= s;
        float u0 = gu[(long)win * 2 + 0], u1 = gu[(long)win * 2 + 1];
        float q0 = -logf(-logf(u0 + 1e-10f) + 1e-10f);
        float q1 = -logf(-logf(u1 + 1e-10f) + 1e-10f);
        g_mask[win] = (p0 + q0 >= p1 + q1) ? 1.f : 0.f;
    }
}

// ---------------- bilinear flow warp ----------------
__global__ __launch_bounds__(256) void warp_kernel(const float* __restrict__ x)
{
    int idx = blockIdx.x * 256 + threadIdx.x;
    int b = idx >> 16, p = idx & 65535;
    int h = p >> 8, w = p & 255;
    float fx = g_off[(long)b * 2 * HW + p];
    float fy = g_off[(long)b * 2 * HW + HW + p];
    float sx = fminf(fmaxf((float)w + fx, 0.f), 255.f);
    float sy = fminf(fmaxf((float)h + fy, 0.f), 255.f);
    float x0f = floorf(sx), y0f = floorf(sy);
    float x1f = fminf(x0f + 1.f, 255.f), y1f = fminf(y0f + 1.f, 255.f);
    float wx = sx - x0f, wy = sy - y0f;
    int x0 = (int)x0f, x1 = (int)x1f, y0 = (int)y0f, y1 = (int)y1f;
    float w00 = (1.f - wx) * (1.f - wy), w01 = wx * (1.f - wy);
    float w10 = (1.f - wx) * wy,        w11 = wx * wy;
    int i00 = y0 * 256 + x0, i01 = y0 * 256 + x1;
    int i10 = y1 * 256 + x0, i11 = y1 * 256 + x1;
    const float* xb = x + (long)b * CH * HW;
    float* ob = g_xw + (long)b * CH * HW;
    for (int c = 0; c < CH; c++) {
        const float* xc = xb + (long)c * HW;
        ob[(long)c * HW + p] = w00 * xc[i00] + w01 * xc[i01] + w10 * xc[i10] + w11 * xc[i11];
    }
}

// ---------------- S = Q K^T per masked window ----------------
__global__ __launch_bounds__(256) void sgemm_kernel()
{
    int win = blockIdx.y;
    if (g_mask[win] == 0.f) return;
    __shared__ float As[64][17];
    __shared__ float Bs[64][17];
    int tile = blockIdx.x;
    int i0 = (tile >> 2) * 64, j0 = (tile & 3) * 64;
    int tx = threadIdx.x & 15, ty = threadIdx.x >> 4;
    const float* A  = g_qw + (long)win * 256 * CH;
    const float* Bm = g_kw + (long)win * 256 * CH;
    float acc[4][4] = {};
    for (int k0 = 0; k0 < CH; k0 += 16) {
#pragma unroll
        for (int l = 0; l < 4; l++) {
            int e = threadIdx.x + 256 * l;
            int r = e >> 4, k = e & 15;
            As[r][k] = A [(long)(i0 + r) * CH + k0 + k];
            Bs[r][k] = Bm[(long)(j0 + r) * CH + k0 + k];
        }
        __syncthreads();
#pragma unroll
        for (int k = 0; k < 16; k++) {
            float av[4], bv[4];
#pragma unroll
            for (int i = 0; i < 4; i++) av[i] = As[ty + 16 * i][k];
#pragma unroll
            for (int j = 0; j < 4; j++) bv[j] = Bs[tx + 16 * j][k];
#pragma unroll
            for (int i = 0; i < 4; i++)
#pragma unroll
                for (int j = 0; j < 4; j++) acc[i][j] += av[i] * bv[j];
        }
        __syncthreads();
    }
    float* Sw = g_S + (long)win * 65536;
#pragma unroll
    for (int i = 0; i < 4; i++)
#pragma unroll
        for (int j = 0; j < 4; j++)
            Sw[(long)(i0 + ty + 16 * i) * 256 + j0 + tx + 16 * j] = acc[i][j];
}

// ---------------- row softmax on S ----------------
__global__ __launch_bounds__(256) void softmax_kernel()
{
    int win = blockIdx.x;
    if (g_mask[win] == 0.f) return;
    int warp = threadIdx.x >> 5, lane = threadIdx.x & 31;
    float* Sw = g_S + (long)win * 65536;
    for (int row = warp; row < 256; row += 8) {
        float* r = Sw + row * 256;
        float v[8];
        float mx = -1e30f;
#pragma unroll
        for (int k = 0; k < 8; k++) { v[k] = r[lane + 32 * k]; mx = fmaxf(mx, v[k]); }
#pragma unroll
        for (int o = 16; o > 0; o >>= 1) mx = fmaxf(mx, __shfl_xor_sync(0xffffffffu, mx, o));
        float s = 0.f;
#pragma unroll
        for (int k = 0; k < 8; k++) { v[k] = expf(v[k] - mx); s += v[k]; }
#pragma unroll
        for (int o = 16; o > 0; o >>= 1) s += __shfl_xor_sync(0xffffffffu, s, o);
        float inv = 1.f / s;
#pragma unroll
        for (int k = 0; k < 8; k++) r[lane + 32 * k] = v[k] * inv;
    }
}

// ---------------- out = P @ V or v*sa, scattered to NCHW ----------------
__global__ __launch_bounds__(256) void pv_kernel()
{
    int win = blockIdx.y;
    int b = win >> 8, n = win & 255;
    int wy = n >> 4, wx = n & 15;
    int tile = blockIdx.x;
    int i0 = (tile >> 1) * 64, c0 = (tile & 1) * 64;
    int tx = threadIdx.x & 15, ty = threadIdx.x >> 4;
    const float* vbase = g_cond + (long)b * CD * HW;

    if (g_mask[win] == 0.f) {
#pragma unroll
        for (int ii = 0; ii < 4; ii++)
#pragma unroll
            for (int jj = 0; jj < 4; jj++) {
                int c = c0 + ty + 16 * ii;
                int i = i0 + tx + 16 * jj;
                int p = (wy * 16 + (i >> 4)) * 256 + wx * 16 + (i & 15);
                g_out[(long)b * CH * HW + (long)c * HW + p] =
                    vbase[(long)c * HW + p] * g_sa[(long)b * HW + p];
            }
        return;
    }

    __shared__ float Ps[64][17];
    __shared__ float Vs[16][65];
    const float* Pm = g_S + (long)win * 65536;
    float acc[4][4] = {};
    for (int k0 = 0; k0 < 256; k0 += 16) {
#pragma unroll
        for (int l = 0; l < 4; l++) {
            int e = threadIdx.x + 256 * l;
            int r = e >> 4, k = e & 15;
            Ps[r][k] = Pm[(long)(i0 + r) * 256 + k0 + k];
        }
#pragma unroll
        for (int l = 0; l < 4; l++) {
            int ee = threadIdx.x + 256 * l;
            int cl = ee >> 4, jl = ee & 15;
            int j = k0 + jl;
            int p = (wy * 16 + (j >> 4)) * 256 + wx * 16 + (j & 15);
            Vs[jl][cl] = vbase[(long)(c0 + cl) * HW + p];
        }
        __syncthreads();
#pragma unroll
        for (int k = 0; k < 16; k++) {
            float pvv[4], vv[4];
#pragma unroll
            for (int jj = 0; jj < 4; jj++) pvv[jj] = Ps[tx + 16 * jj][k];
#pragma unroll
            for (int ii = 0; ii < 4; ii++) vv[ii] = Vs[k][ty + 16 * ii];
#pragma unroll
            for (int ii = 0; ii < 4; ii++)
#pragma unroll
                for (int jj = 0; jj < 4; jj++) acc[ii][jj] += pvv[jj] * vv[ii];
        }
        __syncthreads();
    }
#pragma unroll
    for (int ii = 0; ii < 4; ii++)
#pragma unroll
        for (int jj = 0; jj < 4; jj++) {
            int c = c0 + ty + 16 * ii;
            int i = i0 + tx + 16 * jj;
            int p = (wy * 16 + (i >> 4)) * 256 + wx * 16 + (i & 15);
            g_out[(long)b * CH * HW + (long)c * HW + p] = acc[ii][jj];
        }
}

// ---------------- depthwise 5x5 ----------------
__global__ __launch_bounds__(256) void dw5_kernel(
    const float* __restrict__ In, const float* __restrict__ Wt,
    const float* __restrict__ Bias, float* __restrict__ Out, int dil)
{
    long idx = (long)blockIdx.x * 256 + threadIdx.x;
    int p = (int)(idx & 65535);
    int bc = (int)(idx >> 16);
    int c = bc & 127;
    int h = p >> 8, w = p & 255;
    const float* ib = In + (long)bc * HW;
    float acc = Bias[c];
#pragma unroll
    for (int kh = 0; kh < 5; kh++) {
        int hh = h + (kh - 2) * dil;
        if ((unsigned)hh >= 256u) continue;
#pragma unroll
        for (int kw = 0; kw < 5; kw++) {
            int ww = w + (kw - 2) * dil;
            if ((unsigned)ww >= 256u) continue;
            acc += ib[hh * 256 + ww] * Wt[c * 25 + kh * 5 + kw];
        }
    }
    Out[idx] = acc;
}

// ---------------- depthwise 5x5 dil3 + gelu*ca + residual ----------------
__global__ __launch_bounds__(256) void dw5_gelu_kernel(
    const float* __restrict__ In, const float* __restrict__ Wt,
    const float* __restrict__ Bias, float* __restrict__ Out)
{
    long idx = (long)blockIdx.x * 256 + threadIdx.x;
    int p = (int)(idx & 65535);
    int bc = (int)(idx >> 16);
    int c = bc & 127;
    int h = p >> 8, w = p & 255;
    const float* ib = In + (long)bc * HW;
    float acc = Bias[c];
#pragma unroll
    for (int kh = 0; kh < 5; kh++) {
        int hh = h + (kh - 2) * 3;
        if ((unsigned)hh >= 256u) continue;
#pragma unroll
        for (int kw = 0; kw < 5; kw++) {
            int ww = w + (kw - 2) * 3;
            if ((unsigned)ww >= 256u) continue;
            acc += ib[hh * 256 + ww] * Wt[c * 25 + kh * 5 + kw];
        }
    }
    float ge = 0.5f * acc * (1.f + erff(acc * 0.70710678118654752f));
    Out[idx] = ge * g_ca[bc] + g_out[idx];
}

// ---------------- launcher ----------------
extern "C" void kernel_launch(void* const* d_in, const int* in_sizes, int n_in,
                              void* d_out, int out_size)
{
    const float* x    = (const float*)d_in[0];
    const float* cg   = (const float*)d_in[1];
    const float* gu   = (const float*)d_in[2];
    const float* pv_w = (const float*)d_in[3];
    const float* pv_b = (const float*)d_in[4];
    const float* pq_w = (const float*)d_in[5];
    const float* pq_b = (const float*)d_in[6];
    const float* pk_w = (const float*)d_in[7];
    const float* pk_b = (const float*)d_in[8];
    const float* cs1_w = (const float*)d_in[9];
    const float* cs1_b = (const float*)d_in[10];
    const float* cs2_w = (const float*)d_in[11];
    const float* cs2_b = (const float*)d_in[12];
    const float* cs3_w = (const float*)d_in[13];
    const float* cs3_b = (const float*)d_in[14];
    const float* po_w  = (const float*)d_in[15];
    const float* po_b  = (const float*)d_in[16];
    const float* rin_w = (const float*)d_in[17];
    const float* rin_b = (const float*)d_in[18];
    const float* roff1_w = (const float*)d_in[19];
    const float* roff1_b = (const float*)d_in[20];
    const float* roff2_w = (const float*)d_in[21];
    const float* roff2_b = (const float*)d_in[22];
    const float* rm1_w = (const float*)d_in[23];
    const float* rm1_b = (const float*)d_in[24];
    const float* rm2_w = (const float*)d_in[25];
    const float* rm2_b = (const float*)d_in[26];
    const float* rca_w = (const float*)d_in[27];
    const float* rca_b = (const float*)d_in[28];
    const float* rsa_w = (const float*)d_in[29];
    const float* rsa_b = (const float*)d_in[30];
    float* out = (float*)d_out;

    float *p_cond, *p_f, *p_xw, *p_qw, *p_kw, *p_out, *p_b1, *p_b2;
    __nv_bfloat16 *p_whi, *p_wlo;
    cudaGetSymbolAddress((void**)&p_cond, g_cond);
    cudaGetSymbolAddress((void**)&p_f,    g_f);
    cudaGetSymbolAddress((void**)&p_xw,   g_xw);
    cudaGetSymbolAddress((void**)&p_qw,   g_qw);
    cudaGetSymbolAddress((void**)&p_kw,   g_kw);
    cudaGetSymbolAddress((void**)&p_out,  g_out);
    cudaGetSymbolAddress((void**)&p_b1,   g_b1);
    cudaGetSymbolAddress((void**)&p_b2,   g_b2);
    cudaGetSymbolAddress((void**)&p_whi,  g_whi);
    cudaGetSymbolAddress((void**)&p_wlo,  g_wlo);

    static int attr_set = 0;
    if (!attr_set) {
        cudaFuncSetAttribute(conv_mma, cudaFuncAttributeMaxDynamicSharedMemorySize,
                             CONV_SMEM);
        attr_set = 1;
    }

    dim3 blk(256);
    int cgrid = (BATCH * HW / 128) / TPB_CONV;   // 1024

    // 1. v = pv conv -> cond channels 0..127  (HMMA)
    w_prep<<<64, blk>>>(pv_w, p_whi, p_wlo);
    conv_mma<<<cgrid, blk, CONV_SMEM>>>(x, (long)CH * HW, p_whi, p_wlo, pv_b,
                                        p_cond, (long)CD * HW, 0);
    // 2. cond extra channels
    fill_cond<<<BATCH * HW / 256, blk>>>(cg);
    // 3. f = leaky(rin conv)  (fp32, ragged K=131)
    gemm1x1<<<dim3(HW / 64, 1, BATCH), blk>>>(p_cond, CD * HW, rin_w, rin_b,
                                              p_f, C4 * HW, CD, C4, 1);
    // 4. offsets
    roff_kernel<<<BATCH * HW / 256, blk>>>(roff1_w, roff1_b, roff2_w, roff2_b);
    // 5. predictor stats
    fmc_kernel<<<BATCH * HW / 256, blk>>>();
    fm_kernel<<<BATCH * C4, blk>>>();
    ca_kernel<<<1, BATCH * CH>>>(rca_w, rca_b);
    sa_kernel<<<BATCH * HW / 256, blk>>>(rsa_w, rsa_b);
    // 6. hard mask
    mask_kernel<<<BATCH * NWIN, blk>>>(rm1_w, rm1_b, rm2_w, rm2_b, gu);
    // 7. flow warp
    warp_kernel<<<BATCH * HW / 256, blk>>>(x);
    // 8. q/k projections into windowed layout (HMMA)
    w_prep<<<64, blk>>>(pq_w, p_whi, p_wlo);
    conv_mma<<<cgrid, blk, CONV_SMEM>>>(p_xw, (long)CH * HW, p_whi, p_wlo, pq_b,
                                        p_qw, 0, 1);
    w_prep<<<64, blk>>>(pk_w, p_whi, p_wlo);
    conv_mma<<<cgrid, blk, CONV_SMEM>>>(p_xw, (long)CH * HW, p_whi, p_wlo, pk_b,
                                        p_kw, 0, 1);
    // 9. attention
    sgemm_kernel<<<dim3(16, BATCH * NWIN), blk>>>();
    softmax_kernel<<<BATCH * NWIN, blk>>>();
    pv_kernel<<<dim3(8, BATCH * NWIN), blk>>>();
    // 10. cs chain
    w_prep<<<64, blk>>>(cs1_w, p_whi, p_wlo);
    conv_mma<<<cgrid, blk, CONV_SMEM>>>(p_out, (long)CH * HW, p_whi, p_wlo, cs1_b,
                                        p_b1, (long)CH * HW, 0);
    dw5_kernel<<<(BATCH * CH * HW) / 256, blk>>>(p_b1, cs2_w, cs2_b, p_b2, 1);
    dw5_gelu_kernel<<<(BATCH * CH * HW) / 256, blk>>>(p_b2, cs3_w, cs3_b, p_b1);
    // 11. final projection (HMMA)
    w_prep<<<64, blk>>>(po_w, p_whi, p_wlo);
    conv_mma<<<cgrid, blk, CONV_SMEM>>>(p_b1, (long)CH * HW, p_whi, p_wlo, po_b,
                                        out, (long)CH * HW, 0);
    (void)in_sizes; (void)n_in; (void)out_size;
}